// round 8
// baseline (speedup 1.0000x reference)
#include <cuda_runtime.h>
#include <cstdint>

// Problem constants
#define Bsz 32
#define Lsz 4096
#define Isz 128
#define Hsz 256
#define Osz 128
#define NDELAY 5      // delay line length (DELAY+1)

// Scratch (static device globals: allocation-free per harness rules)
__device__ float g_xz[Bsz * Lsz * Hsz];
__device__ float g_xh[Bsz * Lsz * Hsz];
__device__ float g_hs[Bsz * Lsz * Hsz];

// ---------------------------------------------------------------------------
// Generic fp32 tiled GEMM with bias: C[M,N] = A[M,K] @ B[K,N] + bias[N]
// ---------------------------------------------------------------------------
__global__ void __launch_bounds__(256) gemm_bias(
    const float* __restrict__ A, const float* __restrict__ Bm,
    const float* __restrict__ bias, float* __restrict__ C,
    int M, int K, int N)
{
    __shared__ float sA[64][68];
    __shared__ float sB[64][68];

    const int m0  = blockIdx.x << 6;
    const int n0  = blockIdx.y << 6;
    const int tid = threadIdx.x;
    const int tx  = tid & 15;
    const int ty  = tid >> 4;

    float acc[4][4];
#pragma unroll
    for (int i = 0; i < 4; i++)
#pragma unroll
        for (int j = 0; j < 4; j++) acc[i][j] = 0.f;

    for (int kk = 0; kk < K; kk += 64) {
#pragma unroll
        for (int i = 0; i < 4; i++) {
            int lin = tid + (i << 8);
            int r   = lin >> 4;
            int c   = (lin & 15) << 2;
            *(float4*)&sA[r][c] = *(const float4*)&A[(size_t)(m0 + r) * K + kk + c];
            *(float4*)&sB[r][c] = *(const float4*)&Bm[(size_t)(kk + r) * N + n0 + c];
        }
        __syncthreads();

#pragma unroll 16
        for (int k = 0; k < 64; k++) {
            float a0 = sA[(ty << 2) + 0][k];
            float a1 = sA[(ty << 2) + 1][k];
            float a2 = sA[(ty << 2) + 2][k];
            float a3 = sA[(ty << 2) + 3][k];
            float4 bv = *(float4*)&sB[k][tx << 2];
            acc[0][0] += a0 * bv.x; acc[0][1] += a0 * bv.y;
            acc[0][2] += a0 * bv.z; acc[0][3] += a0 * bv.w;
            acc[1][0] += a1 * bv.x; acc[1][1] += a1 * bv.y;
            acc[1][2] += a1 * bv.z; acc[1][3] += a1 * bv.w;
            acc[2][0] += a2 * bv.x; acc[2][1] += a2 * bv.y;
            acc[2][2] += a2 * bv.z; acc[2][3] += a2 * bv.w;
            acc[3][0] += a3 * bv.x; acc[3][1] += a3 * bv.y;
            acc[3][2] += a3 * bv.z; acc[3][3] += a3 * bv.w;
        }
        __syncthreads();
    }

    float4 bb = *(const float4*)&bias[n0 + (tx << 2)];
#pragma unroll
    for (int i = 0; i < 4; i++) {
        float4 o;
        o.x = acc[i][0] + bb.x;
        o.y = acc[i][1] + bb.y;
        o.z = acc[i][2] + bb.z;
        o.w = acc[i][3] + bb.w;
        *(float4*)&C[(size_t)(m0 + (ty << 2) + i) * N + n0 + (tx << 2)] = o;
    }
}

// ---------------------------------------------------------------------------
// Fast-math helpers (ex2/rcp approx: rel err ~1e-7)
// ---------------------------------------------------------------------------
__device__ __forceinline__ float ex2_fast(float x) {
    float r; asm("ex2.approx.f32 %0, %1;" : "=f"(r) : "f"(x)); return r;
}
__device__ __forceinline__ float rcp_fast(float x) {
    float r; asm("rcp.approx.f32 %0, %1;" : "=f"(r) : "f"(x)); return r;
}
__device__ __forceinline__ float sigmoid_fast(float x) {
    return rcp_fast(1.f + ex2_fast(-1.4426950408889634f * x));
}
__device__ __forceinline__ float tanh_fast(float x) {
    float e = ex2_fast(2.885390081777927f * x);
    return (e - 1.f) * rcp_fast(e + 1.f);
}

// Packed f32x2 dot: 64 floats (16B-aligned shared ptr) . 32 packed weight pairs
__device__ __forceinline__ float dot64_f32x2(const float* p, const uint64_t* w) {
    const ulonglong2* v = (const ulonglong2*)p;
    uint64_t a0 = 0, a1 = 0, a2 = 0, a3 = 0;
#pragma unroll
    for (int i = 0; i < 8; i++) {
        ulonglong2 t = v[i];
        asm("fma.rn.f32x2 %0, %1, %2, %0;" : "+l"(a0) : "l"(t.x), "l"(w[2*i]));
        asm("fma.rn.f32x2 %0, %1, %2, %0;" : "+l"(a1) : "l"(t.y), "l"(w[2*i+1]));
    }
#pragma unroll
    for (int i = 8; i < 16; i++) {
        ulonglong2 t = v[i];
        asm("fma.rn.f32x2 %0, %1, %2, %0;" : "+l"(a2) : "l"(t.x), "l"(w[2*i]));
        asm("fma.rn.f32x2 %0, %1, %2, %0;" : "+l"(a3) : "l"(t.y), "l"(w[2*i+1]));
    }
    uint64_t s01, s23, s;
    asm("add.rn.f32x2 %0, %1, %2;" : "=l"(s01) : "l"(a0), "l"(a1));
    asm("add.rn.f32x2 %0, %1, %2;" : "=l"(s23) : "l"(a2), "l"(a3));
    asm("add.rn.f32x2 %0, %1, %2;" : "=l"(s)   : "l"(s01), "l"(s23));
    float lo, hi;
    asm("mov.b64 {%0, %1}, %2;" : "=f"(lo), "=f"(hi) : "l"(s));
    return lo + hi;
}

__device__ __forceinline__ uint64_t pack2(float lo, float hi) {
    uint64_t r; asm("mov.b64 %0, {%1, %2};" : "=l"(r) : "f"(lo), "f"(hi)); return r;
}

__device__ __forceinline__ void mbar_expect_tx(uint32_t mbar, uint32_t bytes) {
    asm volatile("mbarrier.arrive.expect_tx.shared.b64 _, [%0], %1;"
                 :: "r"(mbar), "r"(bytes) : "memory");
}

__device__ __forceinline__ void mbar_wait(uint32_t mbar, uint32_t parity) {
    asm volatile(
        "{\n\t"
        ".reg .pred P;\n\t"
        "WAIT_%=:\n\t"
        "mbarrier.try_wait.parity.acquire.cluster.shared::cta.b64 P, [%0], %1, 10000000;\n\t"
        "@!P bra WAIT_%=;\n\t"
        "}"
        :: "r"(mbar), "r"(parity) : "memory");
}

// DSMEM bulk copy: local smem -> peer smem, complete_tx to peer's mbarrier.
__device__ __forceinline__ void bulk_s2s(uint32_t dst, uint32_t src,
                                         uint32_t bytes, uint32_t mbar) {
    asm volatile(
        "cp.async.bulk.shared::cluster.shared::cta.mbarrier::complete_tx::bytes "
        "[%0], [%1], %2, [%3];"
        :: "r"(dst), "r"(src), "r"(bytes), "r"(mbar) : "memory");
}

__device__ __forceinline__ void fence_async() {
    asm volatile("fence.proxy.async.shared::cta;" ::: "memory");
}

// ---------------------------------------------------------------------------
// Sequential MGRU scan — bulk-DSMEM exchange, 8 mbarrier arrivals per step.
//
// 32 clusters x 4 CTAs, one cluster per batch row; CTA owns 64 hidden cols,
// Uz/Uh column slices in registers (f32x2 pairs).
//
// Per step t, CTA's mb[t&1] expects 2048 tx-bytes delivered as 8 bulk copies
// (4 sources x [a-chunk 256B + h-chunk 256B]):
//   abuf[t&1]  <- a(t)  = z(t)*h(t-1)   (pushed at end of step t-1)
//   hist[(t-1)%5] <- h(t-1)             (pushed at end of step t-1)
// z(t+1) reads hist[(t+1)%5] = h(t-4) (>=2 phases of slack). Staging is
// double-buffered; stage[p] restaged at step t+1 is ordered after all peers'
// reads (our wait(t+1) <= peers pushed a(t+1) <= peers' wait(t) <= our copies
// arrived => source side consumed). One elected waiter per warp + __syncwarp
// keeps barrier polling to 8 threads.
// ---------------------------------------------------------------------------
__global__ void __launch_bounds__(256, 1) __cluster_dims__(4, 1, 1)
mgru_scan(const float* __restrict__ xz, const float* __restrict__ xh,
          const float* __restrict__ Uz, const float* __restrict__ Uh,
          float* __restrict__ hs)
{
    __shared__ __align__(16) float pool[(NDELAY + 2) * Hsz];  // hist[5] + abuf[2]
    __shared__ __align__(16) float stage[2][128];             // [a(64) | h(64)]
    __shared__ __align__(8) unsigned long long mb[2];
    float* hist = pool;
    const int ABUF = NDELAY * Hsz;

    const int rank = blockIdx.x & 3;
    const int b    = blockIdx.x >> 2;
    const int tid  = threadIdx.x;
    const int w    = tid >> 5;
    const int lane = tid & 31;
    const int ks   = lane & 3;                // K-slice id (4 slices of 64)
    const int cw   = lane >> 2;               // col-within-warp
    const int col  = w * 8 + cw;              // col within CTA (0..63)
    const int jglob = rank * 64 + col;        // global hidden column

    // Register-resident packed weight slices (64 K-values -> 32 f32x2 pairs)
    uint64_t wz2[32], wh2[32];
    {
        const float* uz = Uz + (size_t)(ks * 64) * Hsz + jglob;
        const float* uh = Uh + (size_t)(ks * 64) * Hsz + jglob;
#pragma unroll
        for (int i = 0; i < 32; i++) {
            wz2[i] = pack2(uz[(size_t)(2*i) * Hsz], uz[(size_t)(2*i+1) * Hsz]);
            wh2[i] = pack2(uh[(size_t)(2*i) * Hsz], uh[(size_t)(2*i+1) * Hsz]);
        }
    }

    if (tid == 0) {
        uint32_t m0 = (uint32_t)__cvta_generic_to_shared(&mb[0]);
        asm volatile("mbarrier.init.shared.b64 [%0], 1;" :: "r"(m0) : "memory");
        asm volatile("mbarrier.init.shared.b64 [%0], 1;" :: "r"(m0 + 8) : "memory");
    }
    for (int i = tid; i < (NDELAY + 2) * Hsz; i += 256) pool[i] = 0.f;
    for (int i = tid; i < 256; i += 256) (&stage[0][0])[i] = 0.f;
    __syncthreads();
    // all CTAs' mbarriers + zeroed buffers visible before any async traffic
    asm volatile("barrier.cluster.arrive.aligned;" ::: "memory");
    asm volatile("barrier.cluster.wait.aligned;" ::: "memory");

    const uint32_t pool_sa  = (uint32_t)__cvta_generic_to_shared(pool);
    const uint32_t stage_sa = (uint32_t)__cvta_generic_to_shared(&stage[0][0]);
    const uint32_t mb_sa    = (uint32_t)__cvta_generic_to_shared(&mb[0]);
    uint32_t peer_pool, peer_mb;   // in rank `ks`'s SMEM (tid 0..3 -> rank 0..3)
    asm("mapa.shared::cluster.u32 %0, %1, %2;" : "=r"(peer_pool) : "r"(pool_sa), "r"(ks));
    asm("mapa.shared::cluster.u32 %0, %1, %2;" : "=r"(peer_mb)   : "r"(mb_sa),   "r"(ks));

    const float* xzp = xz + (size_t)b * Lsz * Hsz + jglob;
    const float* xhp = xh + (size_t)b * Lsz * Hsz + jglob;
    float*       hsp = hs + (size_t)b * Lsz * Hsz + jglob;

    float h      = 0.f;
    float xh_cur = xhp[0];
    float xz_nxt = xzp[Hsz];
    float xh_nxt = xhp[Hsz];
    float z      = sigmoid_fast(xzp[0]);   // z(0): delayed state is zero

    // Prologue (end of "step -1"): a(0)=0 -> abuf[0], h(-1)=0 -> hist[4], mb[0]
    if (tid < 4) {
        fence_async();
        bulk_s2s(peer_pool + (uint32_t)((ABUF + rank * 64) << 2),
                 stage_sa, 256u, peer_mb);
        bulk_s2s(peer_pool + (uint32_t)((4 * Hsz + rank * 64) << 2),
                 stage_sa + 256u, 256u, peer_mb);
    }

    int slot_r  = 1;  // (t+1)%5 : read h(t-4)
    int slot_wr = 0;  // t%5     : dst slot for h(t) pushed at end of step t

    for (int t = 0; t < Lsz; ++t) {
        const uint32_t boff = (uint32_t)((t & 1) << 3);

        // ---- z(t+1) from delayed state (local; covered by wait(t-1))
        float s = dot64_f32x2(&hist[slot_r * Hsz + ks * 64], wz2);
        s += __shfl_xor_sync(0xffffffffu, s, 1);
        s += __shfl_xor_sync(0xffffffffu, s, 2);
        float zn = sigmoid_fast(s + xz_nxt);

        float xz_p2 = 0.f, xh_p2 = 0.f;
        if (t + 2 < Lsz) {
            xz_p2 = __ldg(xzp + (size_t)(t + 2) * Hsz);
            xh_p2 = __ldg(xhp + (size_t)(t + 2) * Hsz);
        }

        // ---- wait for a(t) + h(t-1): 2048 tx-bytes on mb[t&1]
        if (tid == 0) mbar_expect_tx(mb_sa + boff, 2048u);
        if (lane == 0) mbar_wait(mb_sa + boff, (uint32_t)((t >> 1) & 1));
        __syncwarp();

        // ---- candidate + state update (a(t) in abuf[t&1])
        float sh = dot64_f32x2(&pool[ABUF + (t & 1) * Hsz + ks * 64], wh2);
        sh += __shfl_xor_sync(0xffffffffu, sh, 1);
        sh += __shfl_xor_sync(0xffffffffu, sh, 2);
        float ht = tanh_fast(sh + xh_cur);
        h = h + z * (ht - h);               // (1-z)*h + z*ht
        if (ks == 0) hsp[(size_t)t * Hsz] = h;

        // ---- stage a(t+1)=z(t+1)*h(t) and h(t); push to all 4 peers
        const int p = (t + 1) & 1;
        if (ks == 0) {
            stage[p][col]      = zn * h;
            stage[p][64 + col] = h;
        }
        __syncthreads();
        if (tid < 4 && t + 1 < Lsz) {
            fence_async();
            const uint32_t sb = stage_sa + (uint32_t)(p << 9);
            bulk_s2s(peer_pool + (uint32_t)((ABUF + p * Hsz + rank * 64) << 2),
                     sb, 256u, peer_mb + (uint32_t)(p << 3));
            bulk_s2s(peer_pool + (uint32_t)((slot_wr * Hsz + rank * 64) << 2),
                     sb + 256u, 256u, peer_mb + (uint32_t)(p << 3));
        }

        z = zn;
        xh_cur = xh_nxt;
        xz_nxt = xz_p2;
        xh_nxt = xh_p2;
        slot_r  = (slot_r  == NDELAY - 1) ? 0 : slot_r  + 1;
        slot_wr = (slot_wr == NDELAY - 1) ? 0 : slot_wr + 1;
    }

    // no CTA may exit while peer traffic targeting it may be in flight
    asm volatile("barrier.cluster.arrive.aligned;" ::: "memory");
    asm volatile("barrier.cluster.wait.aligned;" ::: "memory");
}

// Dummy so ncu (6th global launch; 2 harness launches precede ours) captures
// the scan.
__global__ void dummy_k() {}

// ---------------------------------------------------------------------------
// Launch: proj GEMMs -> dummy -> scan -> head GEMM
// ---------------------------------------------------------------------------
extern "C" void kernel_launch(void* const* d_in, const int* in_sizes, int n_in,
                              void* d_out, int out_size)
{
    const float* x  = (const float*)d_in[0];
    const float* Wz = (const float*)d_in[1];
    const float* Uz = (const float*)d_in[2];
    const float* bz = (const float*)d_in[3];
    const float* Wh = (const float*)d_in[4];
    const float* Uh = (const float*)d_in[5];
    const float* bh = (const float*)d_in[6];
    const float* Wo = (const float*)d_in[7];
    const float* bo = (const float*)d_in[8];
    float* y = (float*)d_out;

    float *xz_p = nullptr, *xh_p = nullptr, *hs_p = nullptr;
    cudaGetSymbolAddress((void**)&xz_p, g_xz);
    cudaGetSymbolAddress((void**)&xh_p, g_xh);
    cudaGetSymbolAddress((void**)&hs_p, g_hs);

    const int M = Bsz * Lsz;           // 131072
    dim3 blk(256);

    gemm_bias<<<dim3(M / 64, Hsz / 64), blk>>>(x, Wz, bz, xz_p, M, Isz, Hsz);
    gemm_bias<<<dim3(M / 64, Hsz / 64), blk>>>(x, Wh, bh, xh_p, M, Isz, Hsz);

    dummy_k<<<1, 1>>>();

    mgru_scan<<<Bsz * 4, 256>>>(xz_p, xh_p, Uz, Uh, hs_p);

    gemm_bias<<<dim3(M / 64, Osz / 64), blk>>>(hs_p, Wo, bo, y, M, Hsz, Osz);
}

// round 9
// speedup vs baseline: 2.2524x; 2.2524x over previous
#include <cuda_runtime.h>
#include <cstdint>

// Problem constants
#define Bsz 32
#define Lsz 4096
#define Isz 128
#define Hsz 256
#define Osz 128
#define NDELAY 5      // delay line length (DELAY+1)

// Scratch (static device globals: allocation-free per harness rules)
__device__ float g_xz[Bsz * Lsz * Hsz];
__device__ float g_xh[Bsz * Lsz * Hsz];
__device__ float g_hs[Bsz * Lsz * Hsz];

// ---------------------------------------------------------------------------
// Generic fp32 tiled GEMM with bias: C[M,N] = A[M,K] @ B[K,N] + bias[N]
// ---------------------------------------------------------------------------
__global__ void __launch_bounds__(256) gemm_bias(
    const float* __restrict__ A, const float* __restrict__ Bm,
    const float* __restrict__ bias, float* __restrict__ C,
    int M, int K, int N)
{
    __shared__ float sA[64][68];
    __shared__ float sB[64][68];

    const int m0  = blockIdx.x << 6;
    const int n0  = blockIdx.y << 6;
    const int tid = threadIdx.x;
    const int tx  = tid & 15;
    const int ty  = tid >> 4;

    float acc[4][4];
#pragma unroll
    for (int i = 0; i < 4; i++)
#pragma unroll
        for (int j = 0; j < 4; j++) acc[i][j] = 0.f;

    for (int kk = 0; kk < K; kk += 64) {
#pragma unroll
        for (int i = 0; i < 4; i++) {
            int lin = tid + (i << 8);
            int r   = lin >> 4;
            int c   = (lin & 15) << 2;
            *(float4*)&sA[r][c] = *(const float4*)&A[(size_t)(m0 + r) * K + kk + c];
            *(float4*)&sB[r][c] = *(const float4*)&Bm[(size_t)(kk + r) * N + n0 + c];
        }
        __syncthreads();

#pragma unroll 16
        for (int k = 0; k < 64; k++) {
            float a0 = sA[(ty << 2) + 0][k];
            float a1 = sA[(ty << 2) + 1][k];
            float a2 = sA[(ty << 2) + 2][k];
            float a3 = sA[(ty << 2) + 3][k];
            float4 bv = *(float4*)&sB[k][tx << 2];
            acc[0][0] += a0 * bv.x; acc[0][1] += a0 * bv.y;
            acc[0][2] += a0 * bv.z; acc[0][3] += a0 * bv.w;
            acc[1][0] += a1 * bv.x; acc[1][1] += a1 * bv.y;
            acc[1][2] += a1 * bv.z; acc[1][3] += a1 * bv.w;
            acc[2][0] += a2 * bv.x; acc[2][1] += a2 * bv.y;
            acc[2][2] += a2 * bv.z; acc[2][3] += a2 * bv.w;
            acc[3][0] += a3 * bv.x; acc[3][1] += a3 * bv.y;
            acc[3][2] += a3 * bv.z; acc[3][3] += a3 * bv.w;
        }
        __syncthreads();
    }

    float4 bb = *(const float4*)&bias[n0 + (tx << 2)];
#pragma unroll
    for (int i = 0; i < 4; i++) {
        float4 o;
        o.x = acc[i][0] + bb.x;
        o.y = acc[i][1] + bb.y;
        o.z = acc[i][2] + bb.z;
        o.w = acc[i][3] + bb.w;
        *(float4*)&C[(size_t)(m0 + (ty << 2) + i) * N + n0 + (tx << 2)] = o;
    }
}

// ---------------------------------------------------------------------------
// Fast-math helpers (ex2/rcp approx: rel err ~1e-7)
// ---------------------------------------------------------------------------
__device__ __forceinline__ float ex2_fast(float x) {
    float r; asm("ex2.approx.f32 %0, %1;" : "=f"(r) : "f"(x)); return r;
}
__device__ __forceinline__ float rcp_fast(float x) {
    float r; asm("rcp.approx.f32 %0, %1;" : "=f"(r) : "f"(x)); return r;
}
__device__ __forceinline__ float sigmoid_fast(float x) {
    return rcp_fast(1.f + ex2_fast(-1.4426950408889634f * x));
}
__device__ __forceinline__ float tanh_fast(float x) {
    float e = ex2_fast(2.885390081777927f * x);
    return (e - 1.f) * rcp_fast(e + 1.f);
}

// Packed f32x2 dot over 64 floats with per-thread read rotation `rot` (0..15):
// reads v[(j+rot)&15]; weights must be loaded pre-rotated to match.
// Rotation de-conflicts the smem banks across the 4 ks groups in a warp.
__device__ __forceinline__ float dot64_rot(const float* p, const uint64_t* w,
                                           int rot) {
    const ulonglong2* v = (const ulonglong2*)p;
    uint64_t a0 = 0, a1 = 0, a2 = 0, a3 = 0;
#pragma unroll
    for (int j = 0; j < 8; j++) {
        ulonglong2 t = v[(j + rot) & 15];
        asm("fma.rn.f32x2 %0, %1, %2, %0;" : "+l"(a0) : "l"(t.x), "l"(w[2*j]));
        asm("fma.rn.f32x2 %0, %1, %2, %0;" : "+l"(a1) : "l"(t.y), "l"(w[2*j+1]));
    }
#pragma unroll
    for (int j = 8; j < 16; j++) {
        ulonglong2 t = v[(j + rot) & 15];
        asm("fma.rn.f32x2 %0, %1, %2, %0;" : "+l"(a2) : "l"(t.x), "l"(w[2*j]));
        asm("fma.rn.f32x2 %0, %1, %2, %0;" : "+l"(a3) : "l"(t.y), "l"(w[2*j+1]));
    }
    uint64_t s01, s23, s;
    asm("add.rn.f32x2 %0, %1, %2;" : "=l"(s01) : "l"(a0), "l"(a1));
    asm("add.rn.f32x2 %0, %1, %2;" : "=l"(s23) : "l"(a2), "l"(a3));
    asm("add.rn.f32x2 %0, %1, %2;" : "=l"(s)   : "l"(s01), "l"(s23));
    float lo, hi;
    asm("mov.b64 {%0, %1}, %2;" : "=f"(lo), "=f"(hi) : "l"(s));
    return lo + hi;
}

__device__ __forceinline__ uint64_t pack2(float lo, float hi) {
    uint64_t r; asm("mov.b64 %0, {%1, %2};" : "=l"(r) : "f"(lo), "f"(hi)); return r;
}

__device__ __forceinline__ void mbar_expect_tx(uint32_t mbar, uint32_t bytes) {
    asm volatile("mbarrier.arrive.expect_tx.shared.b64 _, [%0], %1;"
                 :: "r"(mbar), "r"(bytes) : "memory");
}

__device__ __forceinline__ void mbar_wait(uint32_t mbar, uint32_t parity) {
    asm volatile(
        "{\n\t"
        ".reg .pred P;\n\t"
        "WAIT_%=:\n\t"
        "mbarrier.try_wait.parity.acquire.cluster.shared::cta.b64 P, [%0], %1, 10000000;\n\t"
        "@!P bra WAIT_%=;\n\t"
        "}"
        :: "r"(mbar), "r"(parity) : "memory");
}

// DSMEM bulk copy: local smem -> peer smem, complete_tx to peer's mbarrier.
__device__ __forceinline__ void bulk_s2s(uint32_t dst, uint32_t src,
                                         uint32_t bytes, uint32_t mbar) {
    asm volatile(
        "cp.async.bulk.shared::cluster.shared::cta.mbarrier::complete_tx::bytes "
        "[%0], [%1], %2, [%3];"
        :: "r"(dst), "r"(src), "r"(bytes), "r"(mbar) : "memory");
}

__device__ __forceinline__ void fence_async() {
    asm volatile("fence.proxy.async.shared::cta;" ::: "memory");
}

// ---------------------------------------------------------------------------
// Sequential MGRU scan — bulk-DSMEM exchange + bank-conflict-free dots.
//
// 32 clusters x 4 CTAs, one cluster per batch row; CTA owns 64 hidden cols,
// Uz/Uh column slices in registers (f32x2 pairs, PRE-ROTATED by 2*ks so that
// the LDS reads of the 4 ks groups in a warp hit disjoint banks).
//
// Per step t, CTA's mb[t&1] expects 2048 tx-bytes (4 peers x [a 256B + h 256B]):
//   abuf[t&1]     <- a(t) = z(t)*h(t-1)   (pushed at end of step t-1)
//   hist[(t-1)%5] <- h(t-1)               (pushed at end of step t-1)
// z(t+1) reads hist[(t+1)%5] = h(t-4) (>=2 phases of slack). stage[] is
// double-buffered; restage at t+1 is ordered behind peers' reads via the
// wait-chain. One elected waiter per warp + __syncwarp.
// ---------------------------------------------------------------------------
__global__ void __launch_bounds__(256, 1) __cluster_dims__(4, 1, 1)
mgru_scan(const float* __restrict__ xz, const float* __restrict__ xh,
          const float* __restrict__ Uz, const float* __restrict__ Uh,
          float* __restrict__ hs)
{
    __shared__ __align__(1024) float pool[(NDELAY + 2) * Hsz]; // hist[5]+abuf[2]
    __shared__ __align__(16) float stage[2][128];              // [a(64) | h(64)]
    __shared__ __align__(8) unsigned long long mb[2];
    float* hist = pool;
    const int ABUF = NDELAY * Hsz;

    const int rank = blockIdx.x & 3;
    const int b    = blockIdx.x >> 2;
    const int tid  = threadIdx.x;
    const int w    = tid >> 5;
    const int lane = tid & 31;
    const int ks   = lane & 3;                // K-slice id (4 slices of 64)
    const int cw   = lane >> 2;               // col-within-warp
    const int col  = w * 8 + cw;              // col within CTA (0..63)
    const int jglob = rank * 64 + col;        // global hidden column
    const int rot  = ks << 1;                 // bank-deconflict rotation (see dot)

    // Register-resident packed weight slices, PRE-ROTATED:
    // wz2[2j],wz2[2j+1] pair K-indices of vector slot (j+rot)&15.
    uint64_t wz2[32], wh2[32];
    {
        const float* uz = Uz + (size_t)(ks * 64) * Hsz + jglob;
        const float* uh = Uh + (size_t)(ks * 64) * Hsz + jglob;
#pragma unroll
        for (int j = 0; j < 16; j++) {
            int vi = (j + rot) & 15;          // vector slot actually read at j
            int k0 = vi * 4;                  // 4 floats per ulonglong2 slot
            wz2[2*j]   = pack2(uz[(size_t)(k0+0) * Hsz], uz[(size_t)(k0+1) * Hsz]);
            wz2[2*j+1] = pack2(uz[(size_t)(k0+2) * Hsz], uz[(size_t)(k0+3) * Hsz]);
            wh2[2*j]   = pack2(uh[(size_t)(k0+0) * Hsz], uh[(size_t)(k0+1) * Hsz]);
            wh2[2*j+1] = pack2(uh[(size_t)(k0+2) * Hsz], uh[(size_t)(k0+3) * Hsz]);
        }
    }

    if (tid == 0) {
        uint32_t m0 = (uint32_t)__cvta_generic_to_shared(&mb[0]);
        asm volatile("mbarrier.init.shared.b64 [%0], 1;" :: "r"(m0) : "memory");
        asm volatile("mbarrier.init.shared.b64 [%0], 1;" :: "r"(m0 + 8) : "memory");
    }
    for (int i = tid; i < (NDELAY + 2) * Hsz; i += 256) pool[i] = 0.f;
    for (int i = tid; i < 256; i += 256) (&stage[0][0])[i] = 0.f;
    __syncthreads();
    // all CTAs' mbarriers + zeroed buffers visible before any async traffic
    asm volatile("barrier.cluster.arrive.aligned;" ::: "memory");
    asm volatile("barrier.cluster.wait.aligned;" ::: "memory");

    const uint32_t pool_sa  = (uint32_t)__cvta_generic_to_shared(pool);
    const uint32_t stage_sa = (uint32_t)__cvta_generic_to_shared(&stage[0][0]);
    const uint32_t mb_sa    = (uint32_t)__cvta_generic_to_shared(&mb[0]);
    uint32_t peer_pool, peer_mb;   // in rank `ks`'s SMEM (tid 0..3 -> rank 0..3)
    asm("mapa.shared::cluster.u32 %0, %1, %2;" : "=r"(peer_pool) : "r"(pool_sa), "r"(ks));
    asm("mapa.shared::cluster.u32 %0, %1, %2;" : "=r"(peer_mb)   : "r"(mb_sa),   "r"(ks));

    const float* xzp = xz + (size_t)b * Lsz * Hsz + jglob;
    const float* xhp = xh + (size_t)b * Lsz * Hsz + jglob;
    float*       hsp = hs + (size_t)b * Lsz * Hsz + jglob;

    float h      = 0.f;
    float xh_cur = xhp[0];
    float xz_nxt = xzp[Hsz];
    float xh_nxt = xhp[Hsz];
    float z      = sigmoid_fast(xzp[0]);   // z(0): delayed state is zero

    // Prologue (end of "step -1"): a(0)=0 -> abuf[0], h(-1)=0 -> hist[4], mb[0]
    if (tid < 4) {
        fence_async();
        bulk_s2s(peer_pool + (uint32_t)((ABUF + rank * 64) << 2),
                 stage_sa, 256u, peer_mb);
        bulk_s2s(peer_pool + (uint32_t)((4 * Hsz + rank * 64) << 2),
                 stage_sa + 256u, 256u, peer_mb);
    }

    int slot_r  = 1;  // (t+1)%5 : read h(t-4)
    int slot_wr = 0;  // t%5     : dst slot for h(t) pushed at end of step t

    for (int t = 0; t < Lsz; ++t) {
        const uint32_t boff = (uint32_t)((t & 1) << 3);

        // ---- z(t+1) from delayed state (local; covered by wait(t-1))
        float s = dot64_rot(&hist[slot_r * Hsz + ks * 64], wz2, rot);
        s += __shfl_xor_sync(0xffffffffu, s, 1);
        s += __shfl_xor_sync(0xffffffffu, s, 2);
        float zn = sigmoid_fast(s + xz_nxt);

        float xz_p2 = 0.f, xh_p2 = 0.f;
        if (t + 2 < Lsz) {
            xz_p2 = __ldg(xzp + (size_t)(t + 2) * Hsz);
            xh_p2 = __ldg(xhp + (size_t)(t + 2) * Hsz);
        }

        // ---- wait for a(t) + h(t-1): 2048 tx-bytes on mb[t&1]
        if (tid == 0) mbar_expect_tx(mb_sa + boff, 2048u);
        if (lane == 0) mbar_wait(mb_sa + boff, (uint32_t)((t >> 1) & 1));
        __syncwarp();

        // ---- candidate + state update (a(t) in abuf[t&1])
        float sh = dot64_rot(&pool[ABUF + (t & 1) * Hsz + ks * 64], wh2, rot);
        sh += __shfl_xor_sync(0xffffffffu, sh, 1);
        sh += __shfl_xor_sync(0xffffffffu, sh, 2);
        float ht = tanh_fast(sh + xh_cur);
        h = h + z * (ht - h);               // (1-z)*h + z*ht
        if (ks == 0) hsp[(size_t)t * Hsz] = h;

        // ---- stage a(t+1)=z(t+1)*h(t) and h(t); push to all 4 peers
        const int p = (t + 1) & 1;
        if (ks == 0) {
            stage[p][col]      = zn * h;
            stage[p][64 + col] = h;
        }
        __syncthreads();
        if (tid < 4 && t + 1 < Lsz) {
            fence_async();
            const uint32_t sb = stage_sa + (uint32_t)(p << 9);
            bulk_s2s(peer_pool + (uint32_t)((ABUF + p * Hsz + rank * 64) << 2),
                     sb, 256u, peer_mb + (uint32_t)(p << 3));
            bulk_s2s(peer_pool + (uint32_t)((slot_wr * Hsz + rank * 64) << 2),
                     sb + 256u, 256u, peer_mb + (uint32_t)(p << 3));
        }

        z = zn;
        xh_cur = xh_nxt;
        xz_nxt = xz_p2;
        xh_nxt = xh_p2;
        slot_r  = (slot_r  == NDELAY - 1) ? 0 : slot_r  + 1;
        slot_wr = (slot_wr == NDELAY - 1) ? 0 : slot_wr + 1;
    }

    // no CTA may exit while peer traffic targeting it may be in flight
    asm volatile("barrier.cluster.arrive.aligned;" ::: "memory");
    asm volatile("barrier.cluster.wait.aligned;" ::: "memory");
}

// Dummy so ncu (6th global launch; 2 harness launches precede ours) captures
// the scan.
__global__ void dummy_k() {}

// ---------------------------------------------------------------------------
// Launch: proj GEMMs -> dummy -> scan -> head GEMM
// ---------------------------------------------------------------------------
extern "C" void kernel_launch(void* const* d_in, const int* in_sizes, int n_in,
                              void* d_out, int out_size)
{
    const float* x  = (const float*)d_in[0];
    const float* Wz = (const float*)d_in[1];
    const float* Uz = (const float*)d_in[2];
    const float* bz = (const float*)d_in[3];
    const float* Wh = (const float*)d_in[4];
    const float* Uh = (const float*)d_in[5];
    const float* bh = (const float*)d_in[6];
    const float* Wo = (const float*)d_in[7];
    const float* bo = (const float*)d_in[8];
    float* y = (float*)d_out;

    float *xz_p = nullptr, *xh_p = nullptr, *hs_p = nullptr;
    cudaGetSymbolAddress((void**)&xz_p, g_xz);
    cudaGetSymbolAddress((void**)&xh_p, g_xh);
    cudaGetSymbolAddress((void**)&hs_p, g_hs);

    const int M = Bsz * Lsz;           // 131072
    dim3 blk(256);

    gemm_bias<<<dim3(M / 64, Hsz / 64), blk>>>(x, Wz, bz, xz_p, M, Isz, Hsz);
    gemm_bias<<<dim3(M / 64, Hsz / 64), blk>>>(x, Wh, bh, xh_p, M, Isz, Hsz);

    dummy_k<<<1, 1>>>();

    mgru_scan<<<Bsz * 4, 256>>>(xz_p, xh_p, Uz, Uh, hs_p);

    gemm_bias<<<dim3(M / 64, Osz / 64), blk>>>(hs_p, Wo, bo, y, M, Hsz, Osz);
}

// round 10
// speedup vs baseline: 2.6039x; 1.1560x over previous
#include <cuda_runtime.h>
#include <cstdint>

// Problem constants
#define Bsz 32
#define Lsz 4096
#define Isz 128
#define Hsz 256
#define Osz 128
#define NDELAY 5      // delay line length (DELAY+1)

// Scratch (static device globals: allocation-free per harness rules)
__device__ float g_xz[Bsz * Lsz * Hsz];
__device__ float g_xh[Bsz * Lsz * Hsz];
__device__ float g_hs[Bsz * Lsz * Hsz];

// ---------------------------------------------------------------------------
// Generic fp32 tiled GEMM with bias: C[M,N] = A[M,K] @ B[K,N] + bias[N]
// ---------------------------------------------------------------------------
__global__ void __launch_bounds__(256) gemm_bias(
    const float* __restrict__ A, const float* __restrict__ Bm,
    const float* __restrict__ bias, float* __restrict__ C,
    int M, int K, int N)
{
    __shared__ float sA[64][68];
    __shared__ float sB[64][68];

    const int m0  = blockIdx.x << 6;
    const int n0  = blockIdx.y << 6;
    const int tid = threadIdx.x;
    const int tx  = tid & 15;
    const int ty  = tid >> 4;

    float acc[4][4];
#pragma unroll
    for (int i = 0; i < 4; i++)
#pragma unroll
        for (int j = 0; j < 4; j++) acc[i][j] = 0.f;

    for (int kk = 0; kk < K; kk += 64) {
#pragma unroll
        for (int i = 0; i < 4; i++) {
            int lin = tid + (i << 8);
            int r   = lin >> 4;
            int c   = (lin & 15) << 2;
            *(float4*)&sA[r][c] = *(const float4*)&A[(size_t)(m0 + r) * K + kk + c];
            *(float4*)&sB[r][c] = *(const float4*)&Bm[(size_t)(kk + r) * N + n0 + c];
        }
        __syncthreads();

#pragma unroll 16
        for (int k = 0; k < 64; k++) {
            float a0 = sA[(ty << 2) + 0][k];
            float a1 = sA[(ty << 2) + 1][k];
            float a2 = sA[(ty << 2) + 2][k];
            float a3 = sA[(ty << 2) + 3][k];
            float4 bv = *(float4*)&sB[k][tx << 2];
            acc[0][0] += a0 * bv.x; acc[0][1] += a0 * bv.y;
            acc[0][2] += a0 * bv.z; acc[0][3] += a0 * bv.w;
            acc[1][0] += a1 * bv.x; acc[1][1] += a1 * bv.y;
            acc[1][2] += a1 * bv.z; acc[1][3] += a1 * bv.w;
            acc[2][0] += a2 * bv.x; acc[2][1] += a2 * bv.y;
            acc[2][2] += a2 * bv.z; acc[2][3] += a2 * bv.w;
            acc[3][0] += a3 * bv.x; acc[3][1] += a3 * bv.y;
            acc[3][2] += a3 * bv.z; acc[3][3] += a3 * bv.w;
        }
        __syncthreads();
    }

    float4 bb = *(const float4*)&bias[n0 + (tx << 2)];
#pragma unroll
    for (int i = 0; i < 4; i++) {
        float4 o;
        o.x = acc[i][0] + bb.x;
        o.y = acc[i][1] + bb.y;
        o.z = acc[i][2] + bb.z;
        o.w = acc[i][3] + bb.w;
        *(float4*)&C[(size_t)(m0 + (ty << 2) + i) * N + n0 + (tx << 2)] = o;
    }
}

// ---------------------------------------------------------------------------
// Fast-math helpers (ex2/rcp approx: rel err ~1e-7)
// ---------------------------------------------------------------------------
__device__ __forceinline__ float ex2_fast(float x) {
    float r; asm("ex2.approx.f32 %0, %1;" : "=f"(r) : "f"(x)); return r;
}
__device__ __forceinline__ float rcp_fast(float x) {
    float r; asm("rcp.approx.f32 %0, %1;" : "=f"(r) : "f"(x)); return r;
}
__device__ __forceinline__ float sigmoid_fast(float x) {
    return rcp_fast(1.f + ex2_fast(-1.4426950408889634f * x));
}
__device__ __forceinline__ float tanh_fast(float x) {
    float e = ex2_fast(2.885390081777927f * x);
    return (e - 1.f) * rcp_fast(e + 1.f);
}

// Packed f32x2 dot over 64 floats; all lanes read the SAME addresses
// (whole-warp broadcast -> conflict-free, 1 wavefront per LDS.128).
__device__ __forceinline__ float dot64_bcast(const float* p, const uint64_t* w) {
    const ulonglong2* v = (const ulonglong2*)p;
    uint64_t a0 = 0, a1 = 0, a2 = 0, a3 = 0;
#pragma unroll
    for (int j = 0; j < 8; j++) {
        ulonglong2 t = v[j];
        asm("fma.rn.f32x2 %0, %1, %2, %0;" : "+l"(a0) : "l"(t.x), "l"(w[2*j]));
        asm("fma.rn.f32x2 %0, %1, %2, %0;" : "+l"(a1) : "l"(t.y), "l"(w[2*j+1]));
    }
#pragma unroll
    for (int j = 8; j < 16; j++) {
        ulonglong2 t = v[j];
        asm("fma.rn.f32x2 %0, %1, %2, %0;" : "+l"(a2) : "l"(t.x), "l"(w[2*j]));
        asm("fma.rn.f32x2 %0, %1, %2, %0;" : "+l"(a3) : "l"(t.y), "l"(w[2*j+1]));
    }
    uint64_t s01, s23, s;
    asm("add.rn.f32x2 %0, %1, %2;" : "=l"(s01) : "l"(a0), "l"(a1));
    asm("add.rn.f32x2 %0, %1, %2;" : "=l"(s23) : "l"(a2), "l"(a3));
    asm("add.rn.f32x2 %0, %1, %2;" : "=l"(s)   : "l"(s01), "l"(s23));
    float lo, hi;
    asm("mov.b64 {%0, %1}, %2;" : "=f"(lo), "=f"(hi) : "l"(s));
    return lo + hi;
}

__device__ __forceinline__ uint64_t pack2(float lo, float hi) {
    uint64_t r; asm("mov.b64 %0, {%1, %2};" : "=l"(r) : "f"(lo), "f"(hi)); return r;
}

__device__ __forceinline__ void mbar_expect_tx(uint32_t mbar, uint32_t bytes) {
    asm volatile("mbarrier.arrive.expect_tx.shared.b64 _, [%0], %1;"
                 :: "r"(mbar), "r"(bytes) : "memory");
}

__device__ __forceinline__ void mbar_wait(uint32_t mbar, uint32_t parity) {
    asm volatile(
        "{\n\t"
        ".reg .pred P;\n\t"
        "WAIT_%=:\n\t"
        "mbarrier.try_wait.parity.acquire.cluster.shared::cta.b64 P, [%0], %1, 10000000;\n\t"
        "@!P bra WAIT_%=;\n\t"
        "}"
        :: "r"(mbar), "r"(parity) : "memory");
}

// DSMEM bulk copy: local smem -> peer smem, complete_tx to peer's mbarrier.
__device__ __forceinline__ void bulk_s2s(uint32_t dst, uint32_t src,
                                         uint32_t bytes, uint32_t mbar) {
    asm volatile(
        "cp.async.bulk.shared::cluster.shared::cta.mbarrier::complete_tx::bytes "
        "[%0], [%1], %2, [%3];"
        :: "r"(dst), "r"(src), "r"(bytes), "r"(mbar) : "memory");
}

__device__ __forceinline__ void fence_async() {
    asm volatile("fence.proxy.async.shared::cta;" ::: "memory");
}

// ---------------------------------------------------------------------------
// Sequential MGRU scan — PARTIAL-DOT exchange.
//
// 32 clusters x 4 CTAs, one cluster per batch row. CTA r owns state indices
// G = [64r, 64r+64) BOTH as hidden columns and as k-rows of Uz/Uh. Thread
// tid computes, for global column jp = tid, the k-partial over G:
//     pUh = sum_{k in G} a_k Uh[k, jp],  a = z(t) (.) h(t-1)  (LOCAL chunk!)
//     pUz = sum_{k in G} hd_k Uz[k, jp], hd = h(t-4) local    (4-step slack)
// Partial slices (64+64 floats per destination CTA, 512B) are bulk-pushed to
// all 4 CTAs; each CTA's mb[t&1] expects 2048 tx-bytes. After the wait,
// column owners (threads 0..63) just sum 4 partials + activations.
//
// Buffer-reuse safety:
//   a_loc[p]   : read at step t (parity p) by all threads before the first
//                __syncthreads; rewritten at step t+2 after wait(t+2)>… chain.
//   out_stage[p]: bulk-engine source reads for step t complete before peers'
//                wait(t); our overwrite at t+2 follows our wait(t+1), which
//                follows peers' (t+1)-pushes, which follow peers' wait(t).
//   inbox[p]   : peer rewrite at t+2 follows peer wait(t+1) -> our t+1 push
//                -> our end-sync(t) -> our reads at step t.
//   hd_ring    : slot written at end of step t, read at step t+4 (>=4 syncs).
// ---------------------------------------------------------------------------
__global__ void __launch_bounds__(256, 1) __cluster_dims__(4, 1, 1)
mgru_scan(const float* __restrict__ xz, const float* __restrict__ xh,
          const float* __restrict__ Uz, const float* __restrict__ Uh,
          float* __restrict__ hs)
{
    __shared__ __align__(16) float a_loc[2][64];        // a(t) local chunk
    __shared__ __align__(16) float hd_ring[NDELAY][64]; // local h history
    __shared__ __align__(16) float out_stage[2][512];   // [dst4][pUh64|pUz64]
    __shared__ __align__(16) float inbox[2][512];       // [src4][pUh64|pUz64]
    __shared__ __align__(8) unsigned long long mb[2];

    const int rank = blockIdx.x & 3;
    const int b    = blockIdx.x >> 2;
    const int tid  = threadIdx.x;
    const int lane = tid & 31;
    const int jp   = tid;                 // partial column (global, 0..255)
    const int ks   = tid & 3;             // peer index for bulk pushes (tid<4)

    // Register-resident weight slices: rows k in G, column jp.
    // wX2[i] packs (U[k0+2i, jp], U[k0+2i+1, jp]); k0 = 64*rank.
    uint64_t wz2[32], wh2[32];
    {
        const float* uz = Uz + (size_t)(rank * 64) * Hsz + jp;
        const float* uh = Uh + (size_t)(rank * 64) * Hsz + jp;
#pragma unroll
        for (int i = 0; i < 32; i++) {
            wz2[i] = pack2(uz[(size_t)(2*i) * Hsz], uz[(size_t)(2*i+1) * Hsz]);
            wh2[i] = pack2(uh[(size_t)(2*i) * Hsz], uh[(size_t)(2*i+1) * Hsz]);
        }
    }

    if (tid == 0) {
        uint32_t m0 = (uint32_t)__cvta_generic_to_shared(&mb[0]);
        asm volatile("mbarrier.init.shared.b64 [%0], 1;" :: "r"(m0) : "memory");
        asm volatile("mbarrier.init.shared.b64 [%0], 1;" :: "r"(m0 + 8) : "memory");
    }
    for (int i = tid; i < 2 * 64;        i += 256) (&a_loc[0][0])[i]   = 0.f;
    for (int i = tid; i < NDELAY * 64;   i += 256) (&hd_ring[0][0])[i] = 0.f;
    for (int i = tid; i < 2 * 512;       i += 256) (&out_stage[0][0])[i] = 0.f;
    for (int i = tid; i < 2 * 512;       i += 256) (&inbox[0][0])[i]   = 0.f;
    __syncthreads();
    // all CTAs' mbarriers + zeroed buffers visible before any async traffic
    asm volatile("barrier.cluster.arrive.aligned;" ::: "memory");
    asm volatile("barrier.cluster.wait.aligned;" ::: "memory");

    const uint32_t stage_sa = (uint32_t)__cvta_generic_to_shared(&out_stage[0][0]);
    const uint32_t inbox_sa = (uint32_t)__cvta_generic_to_shared(&inbox[0][0]);
    const uint32_t mb_sa    = (uint32_t)__cvta_generic_to_shared(&mb[0]);
    uint32_t peer_inbox = 0, peer_mb = 0;   // in rank ks's SMEM (tid 0..3)
    asm("mapa.shared::cluster.u32 %0, %1, %2;" : "=r"(peer_inbox) : "r"(inbox_sa), "r"(ks));
    asm("mapa.shared::cluster.u32 %0, %1, %2;" : "=r"(peer_mb)    : "r"(mb_sa),    "r"(ks));

    // Column-owner state (threads 0..63): jglob = 64*rank + tid
    const int jglob = rank * 64 + tid;    // valid for tid < 64
    const float* xzp = xz + (size_t)b * Lsz * Hsz + jglob;
    const float* xhp = xh + (size_t)b * Lsz * Hsz + jglob;
    float*       hsp = hs + (size_t)b * Lsz * Hsz + jglob;

    float h = 0.f, z = 0.f;
    float xh_cur = 0.f, xz_nxt = 0.f, xh_nxt = 0.f;
    if (tid < 64) {
        xh_cur = xhp[0];
        xz_nxt = xzp[Hsz];
        xh_nxt = xhp[Hsz];
        z      = sigmoid_fast(xzp[0]);   // z(0): h(-5) = 0
        // a(0) = z(0)*h(-1) = 0 -> a_loc[0] already zeroed
    }

    int slot_r = 1;  // (t+1)%5 : read h(t-4)
    int slot_w = 0;  // t%5     : write h(t)

    for (int t = 0; t < Lsz; ++t) {
        const int p = t & 1;
        const uint32_t boff = (uint32_t)(p << 3);
        const uint32_t pb   = (uint32_t)(p << 11);   // p*512 floats in bytes

        // ---- partial dots from LOCAL chunks (all 256 threads)
        float pUh = dot64_bcast(&a_loc[p][0], wh2);            // for h(t)
        float pUz = dot64_bcast(&hd_ring[slot_r][0], wz2);     // for z(t+1)
        {
            const int dst = jp >> 6, idx = jp & 63;
            out_stage[p][dst * 128 + idx]      = pUh;
            out_stage[p][dst * 128 + 64 + idx] = pUz;
        }
        __syncthreads();

        // ---- push partial slices to all 4 CTAs (512B each)
        if (tid < 4) {
            fence_async();
            bulk_s2s(peer_inbox + pb + (uint32_t)(rank << 9),
                     stage_sa + pb + (uint32_t)(ks << 9),
                     512u, peer_mb + boff);
        }

        // ---- prefetch (shadow)
        float xz_p2 = 0.f, xh_p2 = 0.f;
        if (tid < 64 && t + 2 < Lsz) {
            xz_p2 = __ldg(xzp + (size_t)(t + 2) * Hsz);
            xh_p2 = __ldg(xhp + (size_t)(t + 2) * Hsz);
        }

        if (tid == 0) mbar_expect_tx(mb_sa + boff, 2048u);

        // ---- only column-owner warps need the wait; others run to the sync
        if (tid < 64) {
            if (lane == 0) mbar_wait(mb_sa + boff, (uint32_t)((t >> 1) & 1));
            __syncwarp();

            // sum 4 partials + activations + state update
            const float* ib = &inbox[p][0];
            float sh = (ib[tid]       + ib[128 + tid])
                     + (ib[256 + tid] + ib[384 + tid]);
            float sz = (ib[64 + tid]       + ib[192 + tid])
                     + (ib[320 + tid] + ib[448 + tid]);
            float ht = tanh_fast(sh + xh_cur);
            h = h + z * (ht - h);                  // h(t)
            float zn = sigmoid_fast(sz + xz_nxt);  // z(t+1)

            a_loc[p ^ 1][tid]   = zn * h;          // a(t+1) local chunk
            hd_ring[slot_w][tid] = h;              // h(t) into ring
            hsp[(size_t)t * Hsz] = h;

            z = zn;
            xh_cur = xh_nxt;
            xz_nxt = xz_p2;
            xh_nxt = xh_p2;
        }
        __syncthreads();

        slot_r = (slot_r == NDELAY - 1) ? 0 : slot_r + 1;
        slot_w = (slot_w == NDELAY - 1) ? 0 : slot_w + 1;
    }

    // no CTA may exit while peer traffic targeting it may be in flight
    asm volatile("barrier.cluster.arrive.aligned;" ::: "memory");
    asm volatile("barrier.cluster.wait.aligned;" ::: "memory");
}

// Dummy so ncu (6th global launch; 2 harness launches precede ours) captures
// the scan.
__global__ void dummy_k() {}

// ---------------------------------------------------------------------------
// Launch: proj GEMMs -> dummy -> scan -> head GEMM
// ---------------------------------------------------------------------------
extern "C" void kernel_launch(void* const* d_in, const int* in_sizes, int n_in,
                              void* d_out, int out_size)
{
    const float* x  = (const float*)d_in[0];
    const float* Wz = (const float*)d_in[1];
    const float* Uz = (const float*)d_in[2];
    const float* bz = (const float*)d_in[3];
    const float* Wh = (const float*)d_in[4];
    const float* Uh = (const float*)d_in[5];
    const float* bh = (const float*)d_in[6];
    const float* Wo = (const float*)d_in[7];
    const float* bo = (const float*)d_in[8];
    float* y = (float*)d_out;

    float *xz_p = nullptr, *xh_p = nullptr, *hs_p = nullptr;
    cudaGetSymbolAddress((void**)&xz_p, g_xz);
    cudaGetSymbolAddress((void**)&xh_p, g_xh);
    cudaGetSymbolAddress((void**)&hs_p, g_hs);

    const int M = Bsz * Lsz;           // 131072
    dim3 blk(256);

    gemm_bias<<<dim3(M / 64, Hsz / 64), blk>>>(x, Wz, bz, xz_p, M, Isz, Hsz);
    gemm_bias<<<dim3(M / 64, Hsz / 64), blk>>>(x, Wh, bh, xh_p, M, Isz, Hsz);

    dummy_k<<<1, 1>>>();

    mgru_scan<<<Bsz * 4, 256>>>(xz_p, xh_p, Uz, Uh, hs_p);

    gemm_bias<<<dim3(M / 64, Osz / 64), blk>>>(hs_p, Wo, bo, y, M, Hsz, Osz);
}